// round 7
// baseline (speedup 1.0000x reference)
#include <cuda_runtime.h>
#include <cuda_bf16.h>
#include <math.h>
#include <stdint.h>

#define NPROP 1000
#define MPAD  1024
#define FM_HW 10000
#define K1    12544
#define HID   1024
#define NCAND 20000
#define MAXDET 100
#define KC    32
#define NMSCAP 10240

typedef __nv_bfloat16 bf;

// ---------------- scratch ----------------
__device__ float g_fmT[FM_HW * 256];
__device__ float g_pooled[NPROP * K1];
__device__ bf g_A0[MPAD*K1], g_A1[MPAD*K1];
__device__ bf g_X1a[MPAD*HID], g_X1b[MPAD*HID];
__device__ bf g_X2a[MPAD*HID], g_X2b[MPAD*HID];
__device__ float g_WHf[HID*128];
__device__ float g_bh[128];
__device__ float g_part[2 * MPAD * HID];
__device__ float g_head[NPROP * 105];
__device__ float4 g_boxes[NCAND], g_boxoff[NCAND];
__device__ float g_cand[NCAND];
__device__ float g_cscore[NCAND];
__device__ int   g_cidx[NCAND];
__device__ float4 g_cboxes[NCAND], g_cboxoff[NCAND];
__device__ int   g_ccount;

// ---------------- PTX helpers ----------------
__device__ __forceinline__ uint32_t s2u(const void* p){
    uint32_t a; asm("{ .reg .u64 t; cvta.to.shared.u64 t, %1; cvt.u32.u64 %0, t; }":"=r"(a):"l"(p)); return a;
}
__device__ __forceinline__ void cpa16(uint32_t s, const void* g){
    asm volatile("cp.async.cg.shared.global [%0], [%1], 16;"::"r"(s),"l"(g):"memory");
}
__device__ __forceinline__ void ldsm4(uint32_t* r, uint32_t addr){
    asm volatile("ldmatrix.sync.aligned.m8n8.x4.shared.b16 {%0,%1,%2,%3}, [%4];"
        :"=r"(r[0]),"=r"(r[1]),"=r"(r[2]),"=r"(r[3]):"r"(addr));
}
__device__ __forceinline__ void mma16816(float* d, const uint32_t* a, const uint32_t* b){
    asm volatile("mma.sync.aligned.m16n8k16.row.col.f32.bf16.bf16.f32 "
        "{%0,%1,%2,%3}, {%4,%5,%6,%7}, {%8,%9}, {%0,%1,%2,%3};"
        :"+f"(d[0]),"+f"(d[1]),"+f"(d[2]),"+f"(d[3])
        :"r"(a[0]),"r"(a[1]),"r"(a[2]),"r"(a[3]),"r"(b[0]),"r"(b[1]));
}
__device__ __forceinline__ void split2(float v, bf& b0, bf& b1){
    b0 = __float2bfloat16(v);
    b1 = __float2bfloat16(v - __bfloat162float(b0));
}

// ---------------- transpose FM ----------------
__global__ void transpose_fm(const float* __restrict__ fm){
    __shared__ float tl[32][33];
    int hw0 = blockIdx.x*32, c0 = blockIdx.y*32, tx = threadIdx.x, ty = threadIdx.y;
#pragma unroll
    for (int j = 0; j < 32; j += 8){
        int hw = hw0 + tx;
        tl[ty+j][tx] = (hw < FM_HW) ? fm[(c0+ty+j)*FM_HW + hw] : 0.f;
    }
    __syncthreads();
#pragma unroll
    for (int j = 0; j < 32; j += 8){
        int hw = hw0 + ty + j;
        if (hw < FM_HW) g_fmT[hw*256 + c0 + tx] = tl[tx][ty+j];
    }
}

// ---------------- ROI align ----------------
__global__ void roi_align_kernel(const float* __restrict__ rois){
    int n = blockIdx.x, t = threadIdx.x;
    int tc = t & 63, cg = t >> 6;
    float4 r = ((const float4*)rois)[n];
    float b0 = r.x*0.125f - 0.5f, b1 = r.y*0.125f - 0.5f;
    float bw = (r.z*0.125f - 0.5f - b0) / 7.0f, bh = (r.w*0.125f - 0.5f - b1) / 7.0f;
    __shared__ int sx0[14], sx1[14], sy0[14], sy1[14];
    __shared__ float swx0[14], swx1[14], swy0[14], swy1[14], svx[14], svy[14];
    if (t < 14){
        int p = t >> 1, s = t & 1;
        float off = (float)p + ((float)s + 0.5f)*0.5f;
        float v = b0 + off*bw;
        svx[t] = (v >= -1.f && v <= 100.f) ? 1.f : 0.f;
        v = fminf(fmaxf(v, 0.f), 99.f);
        float v0 = floorf(v); int i0 = (int)v0;
        sx0[t] = i0; sx1[t] = min(i0+1, 99); swx1[t] = v - v0; swx0[t] = 1.f - (v - v0);
        v = b1 + off*bh;
        svy[t] = (v >= -1.f && v <= 100.f) ? 1.f : 0.f;
        v = fminf(fmaxf(v, 0.f), 99.f);
        v0 = floorf(v); i0 = (int)v0;
        sy0[t] = i0; sy1[t] = min(i0+1, 99); swy1[t] = v - v0; swy0[t] = 1.f - (v - v0);
    }
    __syncthreads();
    const float4* fmT4 = (const float4*)g_fmT;
    float4* outp = (float4*)(g_pooled + (size_t)n*K1);
    for (int cell = cg; cell < 49; cell += 4){
        int ph = cell / 7, pw = cell - ph*7;
        float ax = 0, ay = 0, az = 0, aw = 0;
#pragma unroll
        for (int sy = 0; sy < 2; sy++){
            int j = ph*2 + sy;
            int y0 = sy0[j], y1 = sy1[j];
            float wy0 = swy0[j], wy1 = swy1[j], vy = svy[j];
#pragma unroll
            for (int sx = 0; sx < 2; sx++){
                int k = pw*2 + sx;
                if (vy * svx[k] != 0.f){
                    int x0 = sx0[k], x1 = sx1[k];
                    float w00 = wy0*swx0[k], w01 = wy0*swx1[k], w10 = wy1*swx0[k], w11 = wy1*swx1[k];
                    float4 f00 = fmT4[(y0*100+x0)*64+tc], f01 = fmT4[(y0*100+x1)*64+tc];
                    float4 f10 = fmT4[(y1*100+x0)*64+tc], f11 = fmT4[(y1*100+x1)*64+tc];
                    ax += w00*f00.x + w01*f01.x + w10*f10.x + w11*f11.x;
                    ay += w00*f00.y + w01*f01.y + w10*f10.y + w11*f11.y;
                    az += w00*f00.z + w01*f01.z + w10*f10.z + w11*f11.z;
                    aw += w00*f00.w + w01*f01.w + w10*f10.w + w11*f11.w;
                }
            }
        }
        outp[cell*64 + tc] = make_float4(ax*0.25f, ay*0.25f, az*0.25f, aw*0.25f);
    }
}

// ---------------- pooled [cell*256+c] -> A splits at [c*49+cell] ----------------
__global__ void conv_pooled(){
    extern __shared__ float sm[];
    int n = blockIdx.x, t = threadIdx.x;
    if (n < NPROP){
        const float* s = g_pooled + (size_t)n*K1;
        for (int k = t; k < K1; k += 256) sm[k + (k >> 8)] = s[k];
    }
    __syncthreads();
    size_t b = (size_t)n*K1;
    for (int j = t; j < K1; j += 256){
        float v = 0.f;
        if (n < NPROP){
            int c = j / 49, cell = j - c*49;
            int k = cell*256 + c;
            v = sm[k + (k >> 8)];
        }
        bf h0, h1; split2(v, h0, h1);
        g_A0[b+j] = h0; g_A1[b+j] = h1;
    }
}

// ---------------- heads weights -> fp32 [K=1024][N=128] ----------------
__global__ void conv_heads(const float* __restrict__ wc, const float* __restrict__ bc,
                           const float* __restrict__ wb, const float* __restrict__ bb){
    int h = blockIdx.x;
    for (int k = threadIdx.x; k < HID; k += 256){
        float v = (h < 21) ? wc[k*21 + h] : ((h < 105) ? wb[k*84 + (h-21)] : 0.f);
        g_WHf[k*128 + h] = v;
    }
    if (threadIdx.x == 0)
        g_bh[h] = (h < 21) ? bc[h] : ((h < 105) ? bb[h-21] : 0.f);
}

// ---------------- mma.sync bf16 GEMM, B-side fp32 fused split ----------------
// A: bf16 pairs via cp.async; B: fp32 [K][ldb] loaded direct, split in-kernel.
// BM=128 BN=128, 512 thr (2x8 warps of 64x16), 3 terms, double buffered.
#define GSMEM 81920

__global__ __launch_bounds__(512, 1)
void gemm_mma(const bf* __restrict__ A0, const bf* __restrict__ A1,
              const float* __restrict__ Bw, int ldb,
              const float* __restrict__ bias, int K, int mode,
              float* __restrict__ Cp, float* __restrict__ Oh){
    extern __shared__ char smraw[];
    uint32_t sbase = s2u(smraw);
    int t = threadIdx.x, lane = t & 31, wid = t >> 5;
    int wm = wid & 1, wn = wid >> 1;
    int m0 = blockIdx.y * 128, n0 = blockIdx.x * 128;
    int z = blockIdx.z, nz = gridDim.z;
    int kslice = K / nz, kbase = z * kslice, nch = kslice / KC;

    const bf* srcA[2] = {A0 + (size_t)m0*K, A1 + (size_t)m0*K};

    float acc[4][2][4];
#pragma unroll
    for (int i = 0; i < 4; i++)
#pragma unroll
        for (int j = 0; j < 2; j++)
#pragma unroll
            for (int k = 0; k < 4; k++) acc[i][j][k] = 0.f;

    auto loadA = [&](uint32_t stb, int ko){
#pragma unroll
        for (int i = 0; i < 2; i++){
            int v = t + i*512;
            int tile = v >> 9, idx = v & 511;
            int row = idx >> 2, grp = idx & 3;
            cpa16(stb + tile*10240 + row*80 + grp*16,
                  srcA[tile] + (size_t)row*K + ko + grp*8);
        }
        asm volatile("cp.async.commit_group;":::"memory");
    };
    auto ldgB = [&](float4* r, int ko){
#pragma unroll
        for (int i = 0; i < 2; i++){
            int idx = t + i*512;
            int k = idx >> 5, nq = idx & 31;
            r[i] = *(const float4*)(Bw + (size_t)(ko + k)*ldb + n0 + nq*4);
        }
    };
    auto stB = [&](int bufOff, const float4* r){
#pragma unroll
        for (int i = 0; i < 2; i++){
            int idx = t + i*512;
            int k = idx >> 5, nq = idx & 31;
            const float* f = (const float*)&r[i];
#pragma unroll
            for (int j = 0; j < 4; j++){
                int n = nq*4 + j;
                bf h0, h1; split2(f[j], h0, h1);
                *(bf*)(smraw + bufOff + 20480 + n*80 + k*2) = h0;
                *(bf*)(smraw + bufOff + 30720 + n*80 + k*2) = h1;
            }
        }
    };

    float4 breg[2], breg2[2];
    loadA(sbase, kbase);
    ldgB(breg, kbase);

    uint32_t lsel = (lane & 15)*80 + (lane >> 4)*16;
    for (int c = 0; c < nch; c++){
        int buf = c & 1;
        int bufOff = buf*40960;
        stB(bufOff, breg);
        if (c + 1 < nch){
            loadA(sbase + (buf^1)*40960, kbase + (c+1)*KC);
            ldgB(breg2, kbase + (c+1)*KC);
            asm volatile("cp.async.wait_group 1;":::"memory");
        } else {
            asm volatile("cp.async.wait_group 0;":::"memory");
        }
        __syncthreads();
        uint32_t stb = sbase + bufOff;
#pragma unroll
        for (int ks = 0; ks < 2; ks++){
            uint32_t koff = ks*32;
            uint32_t a[2][4][4], b[2][2][2];
#pragma unroll
            for (int s = 0; s < 2; s++){
#pragma unroll
                for (int i = 0; i < 4; i++)
                    ldsm4(a[s][i], stb + s*10240 + (wm*64 + i*16)*80 + lsel + koff);
                uint32_t r[4];
                ldsm4(r, stb + 20480 + s*10240 + (wn*16)*80 + lsel + koff);
                b[s][0][0] = r[0]; b[s][0][1] = r[2];
                b[s][1][0] = r[1]; b[s][1][1] = r[3];
            }
            const int ta[3] = {0,0,1}, tb[3] = {0,1,0};
#pragma unroll
            for (int e = 0; e < 3; e++)
#pragma unroll
                for (int i = 0; i < 4; i++)
#pragma unroll
                    for (int j = 0; j < 2; j++)
                        mma16816(acc[i][j], a[ta[e]][i], b[tb[e]][j]);
        }
        __syncthreads();
        breg[0] = breg2[0]; breg[1] = breg2[1];
    }

    if (mode == 0){
        float* outp = Cp + (size_t)z * MPAD * HID;
#pragma unroll
        for (int i = 0; i < 4; i++){
            int mr = m0 + wm*64 + i*16 + (lane >> 2);
#pragma unroll
            for (int j = 0; j < 2; j++){
                int nc = n0 + wn*16 + j*8 + (lane & 3)*2;
                *(float2*)(outp + (size_t)mr*HID + nc) = make_float2(acc[i][j][0], acc[i][j][1]);
                *(float2*)(outp + (size_t)(mr+8)*HID + nc) = make_float2(acc[i][j][2], acc[i][j][3]);
            }
        }
    } else {
#pragma unroll
        for (int i = 0; i < 4; i++){
#pragma unroll
            for (int j = 0; j < 2; j++){
                int nc = n0 + wn*16 + j*8 + (lane & 3)*2;
#pragma unroll
                for (int h = 0; h < 2; h++){
                    int m = m0 + wm*64 + i*16 + (lane >> 2) + h*8;
                    if (m < NPROP){
                        if (nc < 105)   Oh[(size_t)m*105 + nc]   = acc[i][j][h*2]   + bias[nc];
                        if (nc+1 < 105) Oh[(size_t)m*105 + nc+1] = acc[i][j][h*2+1] + bias[nc+1];
                    }
                }
            }
        }
    }
}

// ---------------- sum split-K partials + bias + relu + split2 ----------------
__global__ void fixup_split(const float* __restrict__ p, const float* __restrict__ bias,
                            bf* __restrict__ o0, bf* __restrict__ o1){
    int i = blockIdx.x*256 + threadIdx.x;
    float v = fmaxf(p[i] + p[MPAD*HID + i] + bias[i & (HID-1)], 0.f);
    bf h0, h1; split2(v, h0, h1);
    o0[i] = h0; o1[i] = h1;
}

// ---------------- softmax + decode ----------------
__global__ void postproc_kernel(const float* __restrict__ rois){
    int m = blockIdx.x*128 + threadIdx.x;
    if (m >= NPROP) return;
    const float* h = g_head + (size_t)m*105;
    float lg[21], mx = -INFINITY;
#pragma unroll
    for (int c = 0; c < 21; c++){ lg[c] = h[c]; mx = fmaxf(mx, lg[c]); }
    float sum = 0.f;
#pragma unroll
    for (int c = 0; c < 21; c++){ lg[c] = expf(lg[c] - mx); sum += lg[c]; }
    float inv = 1.0f / sum;
    float4 r = ((const float4*)rois)[m];
    float w = r.z - r.x, hh = r.w - r.y;
    float cx = r.x + 0.5f*w, cy = r.y + 0.5f*hh;
#pragma unroll
    for (int c = 1; c < 21; c++){
        float sc = lg[c]*inv;
        float dx = h[21 + c*4 + 0], dy = h[21 + c*4 + 1];
        float dw = h[21 + c*4 + 2], dh = h[21 + c*4 + 3];
        float pcx = dx*w + cx, pcy = dy*hh + cy;
        float pw = expf(dw)*w, ph2 = expf(dh)*hh;
        float x1 = pcx - 0.5f*pw, y1 = pcy - 0.5f*ph2;
        float x2 = pcx + 0.5f*pw, y2 = pcy + 0.5f*ph2;
        int i = m*20 + (c - 1);
        g_boxes[i] = make_float4(x1, y1, x2, y2);
        float off = (float)c * 10000.0f;
        g_boxoff[i] = make_float4(x1 + off, y1 + off, x2 + off, y2 + off);
        g_cand[i] = sc;
    }
}

// ---------------- stable compaction (score > 0.05) ----------------
__global__ void compact_kernel(){
    __shared__ int woff[33];
    __shared__ int sbase;
    int t = threadIdx.x, w = t >> 5, l = t & 31;
    if (t == 0) sbase = 0;
    __syncthreads();
    for (int r = 0; r < NCAND; r += 1024){
        int i = r + t;
        float v = (i < NCAND) ? g_cand[i] : 0.f;
        bool p = (i < NCAND) && (v > 0.05f);
        unsigned bal = __ballot_sync(~0u, p);
        int pre = __popc(bal & ((1u << l) - 1));
        if (l == 0) woff[w] = __popc(bal);
        __syncthreads();
        if (t == 0){
            int s = sbase;
            for (int k = 0; k < 32; k++){ int x = woff[k]; woff[k] = s; s += x; }
            woff[32] = s;
            sbase = s;
        }
        __syncthreads();
        if (p){
            int d = woff[w] + pre;
            g_cscore[d] = v; g_cidx[d] = i;
            g_cboxoff[d] = g_boxoff[i]; g_cboxes[d] = g_boxes[i];
        }
        __syncthreads();
    }
    if (t == 0) g_ccount = sbase;
}

// ---------------- NMS: smem boxes when C small, early exit ----------------
#define NMSSMEM (NMSCAP*4 + NMSCAP*16 + 16)
__global__ void nms_kernel(float* __restrict__ out){
    extern __shared__ char smn[];
    float* s = (float*)smn;
    float4* sbox = (float4*)(smn + NMSCAP*4);
    __shared__ float rv[32]; __shared__ int ri[32];
    __shared__ float4 pbS; __shared__ int s_stop, s_nd;
    __shared__ int keepI[MAXDET]; __shared__ float keepV[MAXDET];
    int t = threadIdx.x;
    int C = g_ccount;
    bool inS = (C <= NMSCAP);
    for (int i = t; i < C; i += 1024){
        s[i] = g_cscore[i];
        if (inS) sbox[i] = g_cboxoff[i];
    }
    if (t == 0){ s_stop = 0; s_nd = 0; }
    __syncthreads();
    float4 pb = make_float4(0,0,0,0); float parea = 0.f; bool have = false;
    for (int it = 0; it < MAXDET; it++){
        float bv = -INFINITY; int bi = 1 << 30;
        for (int i = t; i < C; i += 1024){
            float v = s[i];
            if (have && v > -INFINITY){
                float4 b = inS ? sbox[i] : g_cboxoff[i];
                float ix1 = fmaxf(pb.x, b.x), iy1 = fmaxf(pb.y, b.y);
                float ix2 = fminf(pb.z, b.z), iy2 = fminf(pb.w, b.w);
                float inter = fmaxf(ix2 - ix1, 0.f) * fmaxf(iy2 - iy1, 0.f);
                float A = (b.z - b.x) * (b.w - b.y);
                if (inter / (parea + A - inter + 1e-9f) > 0.5f){ v = -INFINITY; s[i] = v; }
            }
            if (v > bv || (v == bv && i < bi)){ bv = v; bi = i; }
        }
#pragma unroll
        for (int o = 16; o; o >>= 1){
            float ov = __shfl_down_sync(~0u, bv, o);
            int oi = __shfl_down_sync(~0u, bi, o);
            if (ov > bv || (ov == bv && oi < bi)){ bv = ov; bi = oi; }
        }
        if ((t & 31) == 0){ rv[t >> 5] = bv; ri[t >> 5] = bi; }
        __syncthreads();
        if (t < 32){
            bv = rv[t]; bi = ri[t];
#pragma unroll
            for (int o = 16; o; o >>= 1){
                float ov = __shfl_down_sync(~0u, bv, o);
                int oi = __shfl_down_sync(~0u, bi, o);
                if (ov > bv || (ov == bv && oi < bi)){ bv = ov; bi = oi; }
            }
            if (t == 0){
                if (bv > 0.05f){
                    keepI[s_nd] = bi; keepV[s_nd] = bv; s_nd++;
                    pbS = inS ? sbox[bi] : g_cboxoff[bi];
                } else s_stop = 1;
            }
        }
        __syncthreads();
        if (s_stop) break;
        pb = pbS; parea = (pb.z - pb.x) * (pb.w - pb.y); have = true;
        __syncthreads();
    }
    __syncthreads();
    if (t < s_nd){
        int ki = keepI[t];
        float4 b = g_cboxes[ki];
        out[t*4+0] = b.x; out[t*4+1] = b.y; out[t*4+2] = b.z; out[t*4+3] = b.w;
        out[400 + t] = keepV[t];
        out[500 + t] = (float)((g_cidx[ki] % 20) + 1);
    }
}

__global__ void zero_out(float* out, int n){
    int i = blockIdx.x*256 + threadIdx.x;
    if (i < n) out[i] = 0.f;
}

// ---------------- launcher ----------------
extern "C" void kernel_launch(void* const* d_in, const int* in_sizes, int n_in,
                              void* d_out, int out_size){
    const float* fm = (const float*)d_in[0];
    const float* pr = (const float*)d_in[1];
    const float* w1 = (const float*)d_in[2];
    const float* b1 = (const float*)d_in[3];
    const float* w2 = (const float*)d_in[4];
    const float* b2 = (const float*)d_in[5];
    const float* wc = (const float*)d_in[6];
    const float* bc = (const float*)d_in[7];
    const float* wb = (const float*)d_in[8];
    const float* bb = (const float*)d_in[9];
    float* out = (float*)d_out;

    bf *A0,*A1,*X1a,*X1b,*X2a,*X2b;
    float *bh, *head, *part, *whf;
    cudaGetSymbolAddress((void**)&A0, g_A0);   cudaGetSymbolAddress((void**)&A1, g_A1);
    cudaGetSymbolAddress((void**)&X1a, g_X1a); cudaGetSymbolAddress((void**)&X1b, g_X1b);
    cudaGetSymbolAddress((void**)&X2a, g_X2a); cudaGetSymbolAddress((void**)&X2b, g_X2b);
    cudaGetSymbolAddress((void**)&bh, g_bh);   cudaGetSymbolAddress((void**)&head, g_head);
    cudaGetSymbolAddress((void**)&part, g_part);
    cudaGetSymbolAddress((void**)&whf, g_WHf);

    cudaFuncSetAttribute(gemm_mma, cudaFuncAttributeMaxDynamicSharedMemorySize, GSMEM);
    cudaFuncSetAttribute(conv_pooled, cudaFuncAttributeMaxDynamicSharedMemorySize, 50372);
    cudaFuncSetAttribute(nms_kernel, cudaFuncAttributeMaxDynamicSharedMemorySize, NMSSMEM);

    // ordered so gemm_mma (FC1) sits in ncu's profiled launch slot
    transpose_fm<<<dim3(313, 8), dim3(32, 8)>>>(fm);
    roi_align_kernel<<<NPROP, 256>>>(pr);
    conv_pooled<<<MPAD, 256, 50372>>>();

    // FC1: A[1024,12544] @ w1[12544,1024], split-K=2, B fused from fp32
    gemm_mma<<<dim3(8, 8, 2), 512, GSMEM>>>(A0, A1, w1, HID, nullptr, K1, 0, part, nullptr);
    fixup_split<<<MPAD*HID/256, 256>>>(part, b1, X1a, X1b);
    // FC2
    gemm_mma<<<dim3(8, 8, 2), 512, GSMEM>>>(X1a, X1b, w2, HID, nullptr, HID, 0, part, nullptr);
    fixup_split<<<MPAD*HID/256, 256>>>(part, b2, X2a, X2b);
    // heads
    conv_heads<<<128, 256>>>(wc, bc, wb, bb);
    gemm_mma<<<dim3(1, 8, 1), 512, GSMEM>>>(X2a, X2b, whf, 128, bh, HID, 1, nullptr, head);

    zero_out<<<(out_size + 255) / 256, 256>>>(out, out_size);
    postproc_kernel<<<8, 128>>>(pr);
    compact_kernel<<<1, 1024>>>();
    nms_kernel<<<1, 1024, NMSSMEM>>>(out);
}

// round 8
// speedup vs baseline: 1.4644x; 1.4644x over previous
#include <cuda_runtime.h>
#include <cuda_bf16.h>
#include <math.h>
#include <stdint.h>

#define NPROP 1000
#define MPAD  1024
#define FM_HW 10000
#define K1    12544
#define HID   1024
#define NCAND 20000
#define MAXDET 100
#define KC    32
#define NMSCAP 10240

typedef __nv_bfloat16 bf;

// ---------------- scratch ----------------
__device__ float g_fmT[FM_HW * 256];
__device__ float g_pooled[NPROP * K1];
__device__ bf g_A0[MPAD*K1], g_A1[MPAD*K1];
__device__ bf g_W10[HID*K1], g_W11[HID*K1];
__device__ bf g_X1a[MPAD*HID], g_X1b[MPAD*HID];
__device__ bf g_W20[HID*HID], g_W21[HID*HID];
__device__ bf g_X2a[MPAD*HID], g_X2b[MPAD*HID];
__device__ bf g_WH0[128*HID], g_WH1[128*HID];
__device__ float g_bh[128];
__device__ float g_part[2 * MPAD * HID];
__device__ float g_head[NPROP * 105];
__device__ float4 g_boxes[NCAND], g_boxoff[NCAND];
__device__ float g_cand[NCAND];
__device__ float g_cscore[NCAND];
__device__ int   g_cidx[NCAND];
__device__ float4 g_cboxes[NCAND], g_cboxoff[NCAND];
__device__ int   g_ccount;

// ---------------- PTX helpers ----------------
__device__ __forceinline__ uint32_t s2u(const void* p){
    uint32_t a; asm("{ .reg .u64 t; cvta.to.shared.u64 t, %1; cvt.u32.u64 %0, t; }":"=r"(a):"l"(p)); return a;
}
__device__ __forceinline__ void cpa16(uint32_t s, const void* g){
    asm volatile("cp.async.cg.shared.global [%0], [%1], 16;"::"r"(s),"l"(g):"memory");
}
__device__ __forceinline__ void ldsm4(uint32_t* r, uint32_t addr){
    asm volatile("ldmatrix.sync.aligned.m8n8.x4.shared.b16 {%0,%1,%2,%3}, [%4];"
        :"=r"(r[0]),"=r"(r[1]),"=r"(r[2]),"=r"(r[3]):"r"(addr));
}
__device__ __forceinline__ void mma16816(float* d, const uint32_t* a, const uint32_t* b){
    asm volatile("mma.sync.aligned.m16n8k16.row.col.f32.bf16.bf16.f32 "
        "{%0,%1,%2,%3}, {%4,%5,%6,%7}, {%8,%9}, {%0,%1,%2,%3};"
        :"+f"(d[0]),"+f"(d[1]),"+f"(d[2]),"+f"(d[3])
        :"r"(a[0]),"r"(a[1]),"r"(a[2]),"r"(a[3]),"r"(b[0]),"r"(b[1]));
}
__device__ __forceinline__ void split2(float v, bf& b0, bf& b1){
    b0 = __float2bfloat16(v);
    b1 = __float2bfloat16(v - __bfloat162float(b0));
}

// ---------------- transpose FM ----------------
__global__ void transpose_fm(const float* __restrict__ fm){
    __shared__ float tl[32][33];
    int hw0 = blockIdx.x*32, c0 = blockIdx.y*32, tx = threadIdx.x, ty = threadIdx.y;
#pragma unroll
    for (int j = 0; j < 32; j += 8){
        int hw = hw0 + tx;
        tl[ty+j][tx] = (hw < FM_HW) ? fm[(c0+ty+j)*FM_HW + hw] : 0.f;
    }
    __syncthreads();
#pragma unroll
    for (int j = 0; j < 32; j += 8){
        int hw = hw0 + ty + j;
        if (hw < FM_HW) g_fmT[hw*256 + c0 + tx] = tl[tx][ty+j];
    }
}

// ---------------- ROI align ----------------
__global__ void roi_align_kernel(const float* __restrict__ rois){
    int n = blockIdx.x, t = threadIdx.x;
    int tc = t & 63, cg = t >> 6;
    float4 r = ((const float4*)rois)[n];
    float b0 = r.x*0.125f - 0.5f, b1 = r.y*0.125f - 0.5f;
    float bw = (r.z*0.125f - 0.5f - b0) / 7.0f, bh = (r.w*0.125f - 0.5f - b1) / 7.0f;
    __shared__ int sx0[14], sx1[14], sy0[14], sy1[14];
    __shared__ float swx0[14], swx1[14], swy0[14], swy1[14], svx[14], svy[14];
    if (t < 14){
        int p = t >> 1, s = t & 1;
        float off = (float)p + ((float)s + 0.5f)*0.5f;
        float v = b0 + off*bw;
        svx[t] = (v >= -1.f && v <= 100.f) ? 1.f : 0.f;
        v = fminf(fmaxf(v, 0.f), 99.f);
        float v0 = floorf(v); int i0 = (int)v0;
        sx0[t] = i0; sx1[t] = min(i0+1, 99); swx1[t] = v - v0; swx0[t] = 1.f - (v - v0);
        v = b1 + off*bh;
        svy[t] = (v >= -1.f && v <= 100.f) ? 1.f : 0.f;
        v = fminf(fmaxf(v, 0.f), 99.f);
        v0 = floorf(v); i0 = (int)v0;
        sy0[t] = i0; sy1[t] = min(i0+1, 99); swy1[t] = v - v0; swy0[t] = 1.f - (v - v0);
    }
    __syncthreads();
    const float4* fmT4 = (const float4*)g_fmT;
    float4* outp = (float4*)(g_pooled + (size_t)n*K1);
    for (int cell = cg; cell < 49; cell += 4){
        int ph = cell / 7, pw = cell - ph*7;
        float ax = 0, ay = 0, az = 0, aw = 0;
#pragma unroll
        for (int sy = 0; sy < 2; sy++){
            int j = ph*2 + sy;
            int y0 = sy0[j], y1 = sy1[j];
            float wy0 = swy0[j], wy1 = swy1[j], vy = svy[j];
#pragma unroll
            for (int sx = 0; sx < 2; sx++){
                int k = pw*2 + sx;
                if (vy * svx[k] != 0.f){
                    int x0 = sx0[k], x1 = sx1[k];
                    float w00 = wy0*swx0[k], w01 = wy0*swx1[k], w10 = wy1*swx0[k], w11 = wy1*swx1[k];
                    float4 f00 = fmT4[(y0*100+x0)*64+tc], f01 = fmT4[(y0*100+x1)*64+tc];
                    float4 f10 = fmT4[(y1*100+x0)*64+tc], f11 = fmT4[(y1*100+x1)*64+tc];
                    ax += w00*f00.x + w01*f01.x + w10*f10.x + w11*f11.x;
                    ay += w00*f00.y + w01*f01.y + w10*f10.y + w11*f11.y;
                    az += w00*f00.z + w01*f01.z + w10*f10.z + w11*f11.z;
                    aw += w00*f00.w + w01*f01.w + w10*f10.w + w11*f11.w;
                }
            }
        }
        outp[cell*64 + tc] = make_float4(ax*0.25f, ay*0.25f, az*0.25f, aw*0.25f);
    }
}

// ---------------- pooled [cell*256+c] -> A splits at [c*49+cell] ----------------
__global__ void conv_pooled(){
    extern __shared__ float sm[];
    int n = blockIdx.x, t = threadIdx.x;
    if (n < NPROP){
        const float* s = g_pooled + (size_t)n*K1;
        for (int k = t; k < K1; k += 256) sm[k + (k >> 8)] = s[k];
    }
    __syncthreads();
    size_t b = (size_t)n*K1;
    for (int j = t; j < K1; j += 256){
        float v = 0.f;
        if (n < NPROP){
            int c = j / 49, cell = j - c*49;
            int k = cell*256 + c;
            v = sm[k + (k >> 8)];
        }
        bf h0, h1; split2(v, h0, h1);
        g_A0[b+j] = h0; g_A1[b+j] = h1;
    }
}

// ---------------- transpose + split weights: in[R][C] -> out[C][R] ----------------
__global__ void conv_T(const float* __restrict__ in, int R, int C,
                       bf* __restrict__ o0, bf* __restrict__ o1){
    __shared__ float tl[32][33];
    int r0 = blockIdx.y*32, c0 = blockIdx.x*32, tx = threadIdx.x, ty = threadIdx.y;
#pragma unroll
    for (int j = 0; j < 32; j += 8)
        tl[ty+j][tx] = in[(size_t)(r0+ty+j)*C + c0 + tx];
    __syncthreads();
#pragma unroll
    for (int j = 0; j < 32; j += 8){
        float v = tl[tx][ty+j];
        size_t o = (size_t)(c0+ty+j)*R + r0 + tx;
        bf h0, h1; split2(v, h0, h1);
        o0[o] = h0; o1[o] = h1;
    }
}

// ---------------- heads weights -> bf16 pairs [128][1024] ----------------
__global__ void conv_heads(const float* __restrict__ wc, const float* __restrict__ bc,
                           const float* __restrict__ wb, const float* __restrict__ bb){
    int h = blockIdx.x;
    for (int k = threadIdx.x; k < HID; k += 256){
        float v = (h < 21) ? wc[k*21 + h] : ((h < 105) ? wb[k*84 + (h-21)] : 0.f);
        bf h0, h1; split2(v, h0, h1);
        size_t o = (size_t)h*HID + k;
        g_WH0[o] = h0; g_WH1[o] = h1;
    }
    if (threadIdx.x == 0)
        g_bh[h] = (h < 21) ? bc[h] : ((h < 105) ? bb[h-21] : 0.f);
}

// ---------------- mma.sync bf16 GEMM (split-2, 3 terms) ----------------
// BM=128 BN=128, 256 thr = 8 warps (2m x 4n), warp tile 64x32.
// smem/buf: A0,A1,B0,B1 each 128x80B = 10240 -> 40960; double buffered 81920.
#define GSMEM 81920

__global__ __launch_bounds__(256, 1)
void gemm_mma(const bf* __restrict__ A0, const bf* __restrict__ A1,
              const bf* __restrict__ B0, const bf* __restrict__ B1,
              const float* __restrict__ bias, int K, int mode,
              float* __restrict__ Cp, float* __restrict__ Oh){
    extern __shared__ char smraw[];
    uint32_t sbase = s2u(smraw);
    int t = threadIdx.x, lane = t & 31, wid = t >> 5;
    int wm = wid & 1, wn = wid >> 1;            // 2 x 4
    int m0 = blockIdx.y * 128, n0 = blockIdx.x * 128;
    int z = blockIdx.z, nz = gridDim.z;
    int kslice = K / nz, kbase = z * kslice, nch = kslice / KC;

    const bf* src[4] = {A0 + (size_t)m0*K, A1 + (size_t)m0*K,
                        B0 + (size_t)n0*K, B1 + (size_t)n0*K};

    float acc[4][4][4];
#pragma unroll
    for (int i = 0; i < 4; i++)
#pragma unroll
        for (int j = 0; j < 4; j++)
#pragma unroll
            for (int k = 0; k < 4; k++) acc[i][j][k] = 0.f;

    auto loadChunk = [&](uint32_t stb, int ko){
#pragma unroll
        for (int i = 0; i < 8; i++){
            int v = t + i*256;
            int tile = v >> 9, idx = v & 511;
            int row = idx >> 2, grp = idx & 3;
            cpa16(stb + tile*10240 + row*80 + grp*16,
                  src[tile] + (size_t)row*K + ko + grp*8);
        }
        asm volatile("cp.async.commit_group;":::"memory");
    };

    loadChunk(sbase, kbase);

    uint32_t lsel = (lane & 15)*80 + (lane >> 4)*16;
    for (int c = 0; c < nch; c++){
        int buf = c & 1;
        if (c + 1 < nch){
            loadChunk(sbase + (buf^1)*40960, kbase + (c+1)*KC);
            asm volatile("cp.async.wait_group 1;":::"memory");
        } else {
            asm volatile("cp.async.wait_group 0;":::"memory");
        }
        __syncthreads();
        uint32_t stb = sbase + buf*40960;
#pragma unroll
        for (int ks = 0; ks < 2; ks++){
            uint32_t koff = ks*32;
            uint32_t a[2][4][4], b[2][4][2];
#pragma unroll
            for (int s = 0; s < 2; s++){
#pragma unroll
                for (int i = 0; i < 4; i++)
                    ldsm4(a[s][i], stb + s*10240 + (wm*64 + i*16)*80 + lsel + koff);
#pragma unroll
                for (int jj = 0; jj < 2; jj++){
                    uint32_t r[4];
                    ldsm4(r, stb + 20480 + s*10240 + (wn*32 + jj*16)*80 + lsel + koff);
                    b[s][jj*2  ][0] = r[0]; b[s][jj*2  ][1] = r[2];
                    b[s][jj*2+1][0] = r[1]; b[s][jj*2+1][1] = r[3];
                }
            }
            const int ta[3] = {0,0,1}, tb[3] = {0,1,0};
#pragma unroll
            for (int e = 0; e < 3; e++)
#pragma unroll
                for (int i = 0; i < 4; i++)
#pragma unroll
                    for (int j = 0; j < 4; j++)
                        mma16816(acc[i][j], a[ta[e]][i], b[tb[e]][j]);
        }
        __syncthreads();
    }

    if (mode == 0){
        float* outp = Cp + (size_t)z * MPAD * HID;
#pragma unroll
        for (int i = 0; i < 4; i++){
            int mr = m0 + wm*64 + i*16 + (lane >> 2);
#pragma unroll
            for (int j = 0; j < 4; j++){
                int nc = n0 + wn*32 + j*8 + (lane & 3)*2;
                *(float2*)(outp + (size_t)mr*HID + nc) = make_float2(acc[i][j][0], acc[i][j][1]);
                *(float2*)(outp + (size_t)(mr+8)*HID + nc) = make_float2(acc[i][j][2], acc[i][j][3]);
            }
        }
    } else {
#pragma unroll
        for (int i = 0; i < 4; i++){
#pragma unroll
            for (int j = 0; j < 4; j++){
                int nc = n0 + wn*32 + j*8 + (lane & 3)*2;
#pragma unroll
                for (int h = 0; h < 2; h++){
                    int m = m0 + wm*64 + i*16 + (lane >> 2) + h*8;
                    if (m < NPROP){
                        if (nc < 105)   Oh[(size_t)m*105 + nc]   = acc[i][j][h*2]   + bias[nc];
                        if (nc+1 < 105) Oh[(size_t)m*105 + nc+1] = acc[i][j][h*2+1] + bias[nc+1];
                    }
                }
            }
        }
    }
}

// ---------------- sum split-K partials + bias + relu + split2 ----------------
__global__ void fixup_split(const float* __restrict__ p, const float* __restrict__ bias,
                            bf* __restrict__ o0, bf* __restrict__ o1){
    int i = blockIdx.x*256 + threadIdx.x;
    float v = fmaxf(p[i] + p[MPAD*HID + i] + bias[i & (HID-1)], 0.f);
    bf h0, h1; split2(v, h0, h1);
    o0[i] = h0; o1[i] = h1;
}

// ---------------- softmax + decode ----------------
__global__ void postproc_kernel(const float* __restrict__ rois){
    int m = blockIdx.x*128 + threadIdx.x;
    if (m >= NPROP) return;
    const float* h = g_head + (size_t)m*105;
    float lg[21], mx = -INFINITY;
#pragma unroll
    for (int c = 0; c < 21; c++){ lg[c] = h[c]; mx = fmaxf(mx, lg[c]); }
    float sum = 0.f;
#pragma unroll
    for (int c = 0; c < 21; c++){ lg[c] = expf(lg[c] - mx); sum += lg[c]; }
    float inv = 1.0f / sum;
    float4 r = ((const float4*)rois)[m];
    float w = r.z - r.x, hh = r.w - r.y;
    float cx = r.x + 0.5f*w, cy = r.y + 0.5f*hh;
#pragma unroll
    for (int c = 1; c < 21; c++){
        float sc = lg[c]*inv;
        float dx = h[21 + c*4 + 0], dy = h[21 + c*4 + 1];
        float dw = h[21 + c*4 + 2], dh = h[21 + c*4 + 3];
        float pcx = dx*w + cx, pcy = dy*hh + cy;
        float pw = expf(dw)*w, ph2 = expf(dh)*hh;
        float x1 = pcx - 0.5f*pw, y1 = pcy - 0.5f*ph2;
        float x2 = pcx + 0.5f*pw, y2 = pcy + 0.5f*ph2;
        int i = m*20 + (c - 1);
        g_boxes[i] = make_float4(x1, y1, x2, y2);
        float off = (float)c * 10000.0f;
        g_boxoff[i] = make_float4(x1 + off, y1 + off, x2 + off, y2 + off);
        g_cand[i] = sc;
    }
}

// ---------------- stable compaction (score > 0.05) ----------------
__global__ void compact_kernel(){
    __shared__ int woff[33];
    __shared__ int sbase;
    int t = threadIdx.x, w = t >> 5, l = t & 31;
    if (t == 0) sbase = 0;
    __syncthreads();
    for (int r = 0; r < NCAND; r += 1024){
        int i = r + t;
        float v = (i < NCAND) ? g_cand[i] : 0.f;
        bool p = (i < NCAND) && (v > 0.05f);
        unsigned bal = __ballot_sync(~0u, p);
        int pre = __popc(bal & ((1u << l) - 1));
        if (l == 0) woff[w] = __popc(bal);
        __syncthreads();
        if (t == 0){
            int s = sbase;
            for (int k = 0; k < 32; k++){ int x = woff[k]; woff[k] = s; s += x; }
            woff[32] = s;
            sbase = s;
        }
        __syncthreads();
        if (p){
            int d = woff[w] + pre;
            g_cscore[d] = v; g_cidx[d] = i;
            g_cboxoff[d] = g_boxoff[i]; g_cboxes[d] = g_boxes[i];
        }
        __syncthreads();
    }
    if (t == 0) g_ccount = sbase;
}

// ---------------- NMS: smem boxes when C small, early exit ----------------
#define NMSSMEM (NMSCAP*4 + NMSCAP*16 + 16)
__global__ void nms_kernel(float* __restrict__ out){
    extern __shared__ char smn[];
    float* s = (float*)smn;
    float4* sbox = (float4*)(smn + NMSCAP*4);
    __shared__ float rv[32]; __shared__ int ri[32];
    __shared__ float4 pbS; __shared__ int s_stop, s_nd;
    __shared__ int keepI[MAXDET]; __shared__ float keepV[MAXDET];
    int t = threadIdx.x;
    int C = g_ccount;
    bool inS = (C <= NMSCAP);
    for (int i = t; i < C; i += 1024){
        s[i] = g_cscore[i];
        if (inS) sbox[i] = g_cboxoff[i];
    }
    if (t == 0){ s_stop = 0; s_nd = 0; }
    __syncthreads();
    float4 pb = make_float4(0,0,0,0); float parea = 0.f; bool have = false;
    for (int it = 0; it < MAXDET; it++){
        float bv = -INFINITY; int bi = 1 << 30;
        for (int i = t; i < C; i += 1024){
            float v = s[i];
            if (have && v > -INFINITY){
                float4 b = inS ? sbox[i] : g_cboxoff[i];
                float ix1 = fmaxf(pb.x, b.x), iy1 = fmaxf(pb.y, b.y);
                float ix2 = fminf(pb.z, b.z), iy2 = fminf(pb.w, b.w);
                float inter = fmaxf(ix2 - ix1, 0.f) * fmaxf(iy2 - iy1, 0.f);
                float A = (b.z - b.x) * (b.w - b.y);
                if (inter / (parea + A - inter + 1e-9f) > 0.5f){ v = -INFINITY; s[i] = v; }
            }
            if (v > bv || (v == bv && i < bi)){ bv = v; bi = i; }
        }
#pragma unroll
        for (int o = 16; o; o >>= 1){
            float ov = __shfl_down_sync(~0u, bv, o);
            int oi = __shfl_down_sync(~0u, bi, o);
            if (ov > bv || (ov == bv && oi < bi)){ bv = ov; bi = oi; }
        }
        if ((t & 31) == 0){ rv[t >> 5] = bv; ri[t >> 5] = bi; }
        __syncthreads();
        if (t < 32){
            bv = rv[t]; bi = ri[t];
#pragma unroll
            for (int o = 16; o; o >>= 1){
                float ov = __shfl_down_sync(~0u, bv, o);
                int oi = __shfl_down_sync(~0u, bi, o);
                if (ov > bv || (ov == bv && oi < bi)){ bv = ov; bi = oi; }
            }
            if (t == 0){
                if (bv > 0.05f){
                    keepI[s_nd] = bi; keepV[s_nd] = bv; s_nd++;
                    pbS = inS ? sbox[bi] : g_cboxoff[bi];
                } else s_stop = 1;
            }
        }
        __syncthreads();
        if (s_stop) break;
        pb = pbS; parea = (pb.z - pb.x) * (pb.w - pb.y); have = true;
        __syncthreads();
    }
    __syncthreads();
    if (t < s_nd){
        int ki = keepI[t];
        float4 b = g_cboxes[ki];
        out[t*4+0] = b.x; out[t*4+1] = b.y; out[t*4+2] = b.z; out[t*4+3] = b.w;
        out[400 + t] = keepV[t];
        out[500 + t] = (float)((g_cidx[ki] % 20) + 1);
    }
}

__global__ void zero_out(float* out, int n){
    int i = blockIdx.x*256 + threadIdx.x;
    if (i < n) out[i] = 0.f;
}

// ---------------- launcher ----------------
extern "C" void kernel_launch(void* const* d_in, const int* in_sizes, int n_in,
                              void* d_out, int out_size){
    const float* fm = (const float*)d_in[0];
    const float* pr = (const float*)d_in[1];
    const float* w1 = (const float*)d_in[2];
    const float* b1 = (const float*)d_in[3];
    const float* w2 = (const float*)d_in[4];
    const float* b2 = (const float*)d_in[5];
    const float* wc = (const float*)d_in[6];
    const float* bc = (const float*)d_in[7];
    const float* wb = (const float*)d_in[8];
    const float* bb = (const float*)d_in[9];
    float* out = (float*)d_out;

    bf *A0,*A1,*W10,*W11,*X1a,*X1b,*W20,*W21,*X2a,*X2b,*WH0,*WH1;
    float *bh, *head, *part;
    cudaGetSymbolAddress((void**)&A0, g_A0);   cudaGetSymbolAddress((void**)&A1, g_A1);
    cudaGetSymbolAddress((void**)&W10, g_W10); cudaGetSymbolAddress((void**)&W11, g_W11);
    cudaGetSymbolAddress((void**)&X1a, g_X1a); cudaGetSymbolAddress((void**)&X1b, g_X1b);
    cudaGetSymbolAddress((void**)&W20, g_W20); cudaGetSymbolAddress((void**)&W21, g_W21);
    cudaGetSymbolAddress((void**)&X2a, g_X2a); cudaGetSymbolAddress((void**)&X2b, g_X2b);
    cudaGetSymbolAddress((void**)&WH0, g_WH0); cudaGetSymbolAddress((void**)&WH1, g_WH1);
    cudaGetSymbolAddress((void**)&bh, g_bh);   cudaGetSymbolAddress((void**)&head, g_head);
    cudaGetSymbolAddress((void**)&part, g_part);

    cudaFuncSetAttribute(gemm_mma, cudaFuncAttributeMaxDynamicSharedMemorySize, GSMEM);
    cudaFuncSetAttribute(conv_pooled, cudaFuncAttributeMaxDynamicSharedMemorySize, 50372);
    cudaFuncSetAttribute(nms_kernel, cudaFuncAttributeMaxDynamicSharedMemorySize, NMSSMEM);

    transpose_fm<<<dim3(313, 8), dim3(32, 8)>>>(fm);
    roi_align_kernel<<<NPROP, 256>>>(pr);
    conv_pooled<<<MPAD, 256, 50372>>>();
    conv_T<<<dim3(32, 392), dim3(32, 8)>>>(w1, K1, HID, W10, W11);
    conv_T<<<dim3(32, 32), dim3(32, 8)>>>(w2, HID, HID, W20, W21);
    conv_heads<<<128, 256>>>(wc, bc, wb, bb);

    // FC1: [1024,12544] @ [12544,1024], split-K=2
    gemm_mma<<<dim3(8, 8, 2), 256, GSMEM>>>(A0, A1, W10, W11, nullptr, K1, 0, part, nullptr);
    fixup_split<<<MPAD*HID/256, 256>>>(part, b1, X1a, X1b);
    // FC2
    gemm_mma<<<dim3(8, 8, 2), 256, GSMEM>>>(X1a, X1b, W20, W21, nullptr, HID, 0, part, nullptr);
    fixup_split<<<MPAD*HID/256, 256>>>(part, b2, X2a, X2b);
    // heads: N=128 padded
    gemm_mma<<<dim3(1, 8, 1), 256, GSMEM>>>(X2a, X2b, WH0, WH1, bh, HID, 1, nullptr, head);

    zero_out<<<(out_size + 255) / 256, 256>>>(out, out_size);
    postproc_kernel<<<8, 128>>>(pr);
    compact_kernel<<<1, 1024>>>();
    nms_kernel<<<1, 1024, NMSSMEM>>>(out);
}